// round 14
// baseline (speedup 1.0000x reference)
#include <cuda_runtime.h>
#include <math_constants.h>

#define NS     5000
#define SPTS   10
#define NSEG   9
#define KNN    20
#define HH     512
#define WW     512
#define HC     102
#define WC     102
#define NCELL  (HC*WC)
#define NB     16          // bins per axis
#define BINW   32.0f
#define NBINS  (NB*NB)

// ---------------- scratch (static device globals; no runtime allocation) ----
__device__ float4 g_seg[NS * NSEG];     // per segment: -ax, -ay, bx, by
__device__ float  g_d2[NS * NSEG];      // per segment: bx^2+by^2 (ref rounding)
__device__ float4 g_colw[NS];           // rgb + width packed
__device__ int    g_tidx[NCELL * KNN];  // per coarse cell: sorted top-K stroke ids
__device__ float  g_tw[NCELL * KNN];    // per coarse cell: width of slot-k stroke
__device__ int    g_bincnt[NBINS];      // bin build
__device__ int    g_binstart[NBINS + 1];
__device__ int    g_bincur[NBINS];
__device__ float2 g_binloc[NS];         // stroke locations grouped by bin
__device__ int    g_binidx[NS];         // stroke ids grouped by bin

// ---------------- packed f32x2 helpers (sm_103a; per-element IEEE RN) -------
__device__ __forceinline__ unsigned long long f2pack(float lo, float hi) {
    unsigned long long r;
    asm("mov.b64 %0, {%1, %2};" : "=l"(r) : "f"(lo), "f"(hi));
    return r;
}
__device__ __forceinline__ void f2unpack(unsigned long long v, float& lo, float& hi) {
    asm("mov.b64 {%0, %1}, %2;" : "=f"(lo), "=f"(hi) : "l"(v));
}
__device__ __forceinline__ unsigned long long f2add(unsigned long long a, unsigned long long b) {
    unsigned long long r;
    asm("add.rn.f32x2 %0, %1, %2;" : "=l"(r) : "l"(a), "l"(b));
    return r;
}
__device__ __forceinline__ unsigned long long f2mul(unsigned long long a, unsigned long long b) {
    unsigned long long r;
    asm("mul.rn.f32x2 %0, %1, %2;" : "=l"(r) : "l"(a), "l"(b));
    return r;
}

// Branchless correctly-rounded a/b: the div.rn.f32 fast-path sequence; FCHK
// cases cannot occur for these operand ranges (proven bit-identical in R10).
__device__ __forceinline__ float fdiv_exact(float a, float b) {
    float r0;
    asm("rcp.approx.f32 %0, %1;" : "=f"(r0) : "f"(b));
    float e  = __fmaf_rn(-b, r0, 1.0f);
    float r1 = __fmaf_rn(e, r0, r0);
    float q0 = __fmul_rn(a, r1);
    float e2 = __fmaf_rn(-b, q0, a);
    return __fmaf_rn(e2, r1, q0);
}

// ---------------- kernel 0: zero bin counters -------------------------------
__global__ void k_zero() { g_bincnt[threadIdx.x] = 0; }

// ---------------- kernel 1: bezier -> segments (negated a), bin count -------
__global__ void k_bezier(const float* __restrict__ cs, const float* __restrict__ ce,
                         const float* __restrict__ cc, const float* __restrict__ color,
                         const float* __restrict__ loc, const float* __restrict__ width)
{
    int n = blockIdx.x * blockDim.x + threadIdx.x;
    if (n >= NS) return;
    float lx = loc[2*n], ly = loc[2*n+1];
    float Sx = __fadd_rn(cs[2*n],   lx), Sy = __fadd_rn(cs[2*n+1], ly);
    float Ex = __fadd_rn(ce[2*n],   lx), Ey = __fadd_rn(ce[2*n+1], ly);
    float Cx = __fadd_rn(cc[2*n],   lx), Cy = __fadd_rn(cc[2*n+1], ly);
    float dsx = __fsub_rn(Sx, Cx), dsy = __fsub_rn(Sy, Cy);
    float dex = __fsub_rn(Ex, Cx), dey = __fsub_rn(Ey, Cy);
    float step = __fdiv_rn(1.0f, 9.0f);
    float ptx[SPTS], pty[SPTS];
    #pragma unroll
    for (int i = 0; i < SPTS; i++) {
        float t   = __fmul_rn((float)i, step);
        float omt = __fsub_rn(1.0f, t);
        float o2  = __fmul_rn(omt, omt);
        float t2  = __fmul_rn(t, t);
        ptx[i] = __fadd_rn(__fadd_rn(Cx, __fmul_rn(o2, dsx)), __fmul_rn(t2, dex));
        pty[i] = __fadd_rn(__fadd_rn(Cy, __fmul_rn(o2, dsy)), __fmul_rn(t2, dey));
    }
    #pragma unroll
    for (int s = 0; s < NSEG; s++) {
        float bx = __fsub_rn(ptx[s+1], ptx[s]);
        float by = __fsub_rn(pty[s+1], pty[s]);
        g_seg[n*NSEG + s] = make_float4(-ptx[s], -pty[s], bx, by);
        g_d2 [n*NSEG + s] = __fadd_rn(__fmul_rn(bx, bx), __fmul_rn(by, by));
    }
    g_colw[n] = make_float4(color[3*n], color[3*n+1], color[3*n+2], width[n]);

    int bx_ = min(NB-1, (int)(lx * (1.0f/BINW)));
    int by_ = min(NB-1, (int)(ly * (1.0f/BINW)));
    atomicAdd(&g_bincnt[bx_*NB + by_], 1);
}

// ---------------- kernel 2: bin prefix sum (serial, trivial size) -----------
__global__ void k_prep() {
    int acc = 0;
    for (int b = 0; b < NBINS; b++) {
        g_binstart[b] = acc;
        g_bincur[b]   = acc;
        acc += g_bincnt[b];
    }
    g_binstart[NBINS] = acc;
}

// ---------------- kernel 3: scatter strokes into bins -----------------------
__global__ void k_scatter(const float* __restrict__ loc) {
    int n = blockIdx.x * blockDim.x + threadIdx.x;
    if (n >= NS) return;
    float lx = loc[2*n], ly = loc[2*n+1];
    int bx_ = min(NB-1, (int)(lx * (1.0f/BINW)));
    int by_ = min(NB-1, (int)(ly * (1.0f/BINW)));
    int pos = atomicAdd(&g_bincur[bx_*NB + by_], 1);
    g_binloc[pos] = make_float2(lx, ly);
    g_binidx[pos] = n;
}

// ---------------- kernel 4: binned coarse-grid top-K ------------------------
#define CPB    64                 // cells per block (128 threads)
__global__ void __launch_bounds__(CPB*2) k_topk(const float* __restrict__ width)
{
    __shared__ float2 sml[CPB][2][KNN];       // (d, idx-bits)

    int c    = threadIdx.x >> 1;              // local cell
    int part = threadIdx.x & 1;
    int cell = blockIdx.x * CPB + c;
    bool active = (cell < NCELL);
    float px = 0.f, py = 0.f;
    int bx = 0, by = 0;
    if (active) {
        int ci = cell / WC, cj = cell % WC;
        float step = __fdiv_rn(512.0f, 101.0f);   // linspace(0,512,102)
        px = __fmul_rn((float)ci, step);
        py = __fmul_rn((float)cj, step);
        bx = min(NB-1, (int)(px * (1.0f/BINW)));
        by = min(NB-1, (int)(py * (1.0f/BINW)));
    }
    float bd[KNN]; int bi[KNN];
    #pragma unroll
    for (int k = 0; k < KNN; k++) { bd[k] = CUDART_INF_F; bi[k] = 0x7fffffff; }

    int t = 0;
    bool done = !active;
    for (int R = 0; R <= NB; R++) {
        if (active && !done) {
            for (int dy2 = -R; dy2 <= R; dy2++) {
                for (int dx2 = -R; dx2 <= R; dx2++) {
                    if (max(abs(dx2), abs(dy2)) != R) continue;
                    int bxx = bx + dx2, byy = by + dy2;
                    if (bxx < 0 || bxx >= NB || byy < 0 || byy >= NB) continue;
                    if (((t++) & 1) != part) continue;
                    int b = bxx*NB + byy;
                    int j0 = g_binstart[b], j1 = g_binstart[b+1];
                    for (int j = j0; j < j1; j++) {
                        float2 L = g_binloc[j];
                        int ii = g_binidx[j];
                        float dx = __fsub_rn(px, L.x);
                        float dy = __fsub_rn(py, L.y);
                        float d  = __fadd_rn(__fmul_rn(dx, dx), __fmul_rn(dy, dy));
                        if (d < bd[KNN-1] || (d == bd[KNN-1] && ii < bi[KNN-1])) {
                            float id = d; int iv = ii;
                            #pragma unroll
                            for (int q = 0; q < KNN; q++) {
                                bool sw = (id < bd[q]) || (id == bd[q] && iv < bi[q]);
                                float td = bd[q]; int ti = bi[q];
                                if (sw) { bd[q] = id; bi[q] = iv; id = td; iv = ti; }
                            }
                        }
                    }
                }
            }
        }
        float m19 = bd[KNN-1];
        float other = __shfl_xor_sync(0xffffffffu, m19, 1);
        float merged = fminf(m19, other);
        float marg = fminf(fminf(px - (float)(bx-R)*BINW, (float)(bx+R+1)*BINW - px),
                           fminf(py - (float)(by-R)*BINW, (float)(by+R+1)*BINW - py));
        marg *= 0.999f;
        bool covered = (bx-R < 0) && (bx+R >= NB-1) && (by-R < 0) && (by+R >= NB-1);
        if (active && !done)
            done = covered || (marg > 0.0f && merged < marg*marg);
        if (__all_sync(0xffffffffu, done)) break;
    }

    __syncthreads();
    #pragma unroll
    for (int k = 0; k < KNN; k++)
        sml[c][part][k] = make_float2(bd[k], __int_as_float(bi[k]));
    __syncthreads();

    if (active && part == 0) {
        int p0 = 0, p1 = 0;
        #pragma unroll
        for (int k = 0; k < KNN; k++) {
            float2 v0 = sml[c][0][p0];
            float2 v1 = sml[c][1][p1];
            float d0 = v0.x; int i0 = __float_as_int(v0.y);
            float d1 = v1.x; int i1 = __float_as_int(v1.y);
            bool take0 = (d0 < d1) || (d0 == d1 && i0 < i1);
            int besti = take0 ? i0 : i1;
            if (take0) p0++; else p1++;
            g_tidx[cell*KNN + k] = besti;
            g_tw  [cell*KNN + k] = __ldg(width + besti);
        }
    }
}

// ---------------- kernel 5: full-res shading, WARP-PER-CELL -----------------
// One warp = one coarse cell; lanes = the cell's pixels (5x5 typical, max 6x6
// handled by a second predicated pass). All stroke-data loads (idx, seg, d2,
// colw) become warp-uniform -> exactly ONE L1tex wavefront each, eliminating
// the 4-6x wavefront replay of the pixel-tiled mapping. Per-pixel math is
// UNCHANGED -> output bit-identical.
__global__ void __launch_bounds__(256, 3) k_render(float* __restrict__ out)
{
    int wid  = threadIdx.x >> 5;
    int lane = threadIdx.x & 31;
    int cell = blockIdx.x * 8 + wid;
    if (cell >= NCELL) return;              // warp-uniform exit
    int ch = cell / WC, cw = cell % WC;

    // pixel block of this cell: h in [h0,h1), w in [w0,w1)
    // floor(h*51/256) == ch  <=>  h in [ceil(256*ch/51), ceil(256*(ch+1)/51))
    int h0 = (256*ch + 50) / 51,  h1 = (256*(ch+1) + 50) / 51;
    int w0 = (256*cw + 50) / 51,  w1 = (256*(cw+1) + 50) / 51;
    int sh = h1 - h0, sw = w1 - w0;         // 5 or 6
    int npix = sh * sw;                      // 25..36

    const int* idxp = g_tidx + cell * KNN;   // warp-uniform

    float stepf = __fdiv_rn(512.0f, 511.0f); // linspace(0,512,512)

    for (int p = lane; p < npix; p += 32) {
        // exact small-range division p/sw for sw in {5,6}
        int rowp = (sw == 5) ? ((p * 205) >> 10) : ((p * 171) >> 10);
        int colp = p - rowp * sw;
        int h = h0 + rowp;
        int w = w0 + colp;

        float pxf = __fmul_rn((float)h, stepf);
        float pyf = __fmul_rn((float)w, stepf);
        unsigned long long P2 = f2pack(pxf, pyf);

        // half-pixel bilinear for the width resize (smooth path)
        float yc = ((float)h + 0.5f) * 0.19921875f - 0.5f;
        float xc = ((float)w + 0.5f) * 0.19921875f - 0.5f;
        float y0f = floorf(yc), x0f = floorf(xc);
        float fy = yc - y0f,    fx = xc - x0f;
        int y0 = max(0, min(HC-1, (int)y0f));
        int y1 = max(0, min(HC-1, (int)y0f + 1));
        int x0 = max(0, min(WC-1, (int)x0f));
        int x1 = max(0, min(WC-1, (int)x0f + 1));
        const float* pw00 = g_tw + (y0*WC + x0) * KNN;
        const float* pw01 = g_tw + (y0*WC + x1) * KNN;
        const float* pw10 = g_tw + (y1*WC + x0) * KNN;
        const float* pw11 = g_tw + (y1*WC + x1) * KNN;
        float c00 = (1.f-fy)*(1.f-fx), c01 = (1.f-fy)*fx;
        float c10 = fy*(1.f-fx),       c11 = fy*fx;

        float M = -CUDART_INF_F;
        float sum = 0.f, a0 = 0.f, a1 = 0.f, a2 = 0.f, bw = 0.f;
        float D = CUDART_INF_F;

        #pragma unroll 2
        for (int k = 0; k < KNN; k++) {
            int idx = __ldg(idxp + k);      // warp-uniform

            const ulonglong2* sp = reinterpret_cast<const ulonglong2*>(g_seg + idx * NSEG);
            const float*      dp = g_d2 + idx * NSEG;
            float m = CUDART_INF_F;
            #pragma unroll
            for (int s = 0; s < NSEG; s++) {
                ulonglong2 v = __ldg(sp + s);   // uniform broadcast
                float d2 = __ldg(dp + s);       // uniform broadcast
                unsigned long long na2 = v.x, b2 = v.y;
                unsigned long long pa2 = f2add(P2, na2);          // fl(P - a)
                unsigned long long pr  = f2mul(b2, pa2);          // fl(b*pa)
                float plo, phi; f2unpack(pr, plo, phi);
                float dot1 = __fadd_rn(plo, phi);
                float t = fdiv_exact(dot1, d2);
                t = fminf(fmaxf(t, 0.0f), 1.0f);
                float nt = __int_as_float(__float_as_int(t) ^ 0x80000000);
                unsigned long long ntb = f2mul(f2pack(nt, nt), b2);  // -fl(t*b)
                unsigned long long ncl = f2add(na2, ntb);            // -fl(a+tb)
                unsigned long long pc  = f2add(P2, ncl);             // fl(P-closest)
                unsigned long long sq  = f2mul(pc, pc);
                float slo, shi; f2unpack(sq, slo, shi);
                float d = __fadd_rn(slo, shi);
                m = fminf(m, d);
            }
            D = fminf(D, m);

            // r = 100000 * (1 / (1e-8 + m)) — reference rounding (amplified)
            float r = __fmul_rn(100000.0f, __fdiv_rn(1.0f, __fadd_rn(1e-8f, m)));

            float wk = c00*__ldg(pw00+k) + c01*__ldg(pw01+k)
                     + c10*__ldg(pw10+k) + c11*__ldg(pw11+k);
            float4 col = __ldg(&g_colw[idx]);    // uniform broadcast

            // branchless online softmax (smooth path; fast exp safe)
            float newM = fmaxf(r, M);
            float sc = __expf(M - newM);
            float e  = __expf(r - newM);
            sum = sum*sc + e;
            a0  = a0 *sc + e*col.x;
            a1  = a1 *sc + e*col.y;
            a2  = a2 *sc + e*col.z;
            bw  = bw *sc + e*wk;
            M = newM;
        }

        float inv  = __fdividef(1.0f, sum);
        float bs   = bw * inv;
        float mask = __fdividef(1.0f, 1.0f + __expf(-(bs - D)));
        float om   = 1.0f - mask;
        int o = (h * WW + w) * 3;
        out[o+0] = a0*inv*mask + om*0.5f;
        out[o+1] = a1*inv*mask + om*0.5f;
        out[o+2] = a2*inv*mask + om*0.5f;
    }
}

// ---------------- launch ----------------------------------------------------
extern "C" void kernel_launch(void* const* d_in, const int* in_sizes, int n_in,
                              void* d_out, int out_size)
{
    const float* curve_s  = (const float*)d_in[0];
    const float* curve_e  = (const float*)d_in[1];
    const float* curve_c  = (const float*)d_in[2];
    const float* color    = (const float*)d_in[3];
    const float* location = (const float*)d_in[4];
    const float* width    = (const float*)d_in[5];
    float* out = (float*)d_out;

    k_zero<<<1, NBINS>>>();
    k_bezier<<<(NS + 255) / 256, 256>>>(curve_s, curve_e, curve_c, color, location, width);
    k_prep<<<1, 1>>>();
    k_scatter<<<(NS + 255) / 256, 256>>>(location);
    k_topk<<<(NCELL + CPB - 1) / CPB, CPB * 2>>>(width);
    k_render<<<(NCELL + 7) / 8, 256>>>(out);
}

// round 16
// speedup vs baseline: 1.1089x; 1.1089x over previous
#include <cuda_runtime.h>
#include <math_constants.h>

#define NS     5000
#define SPTS   10
#define NSEG   9
#define KNN    20
#define HH     512
#define WW     512
#define HC     102
#define WC     102
#define NCELL  (HC*WC)
#define NB     16          // bins per axis
#define BINW   32.0f
#define NBINS  (NB*NB)

// render smem layout (dynamic)
#define SEG_STRIDE 181                     // 180 used + 1 pad (banks)
#define SM_SEG_OFF 0
#define SM_SEG_SZ  (16 * SEG_STRIDE * 16)                  // ulonglong2
#define SM_D2_OFF  (SM_SEG_OFF + SM_SEG_SZ)
#define SM_D2_SZ   (16 * SEG_STRIDE * 4)                   // float
#define SM_CW_OFF  (SM_D2_OFF + SM_D2_SZ)
#define SM_CW_SZ   (16 * KNN * 16)                         // float4
#define SM_TW_OFF  (SM_CW_OFF + SM_CW_SZ)
#define SM_TW_SZ   (36 * KNN * 4)                          // float
#define SM_TOTAL   (SM_TW_OFF + SM_TW_SZ)                  // 65920 B

// ---------------- scratch (static device globals; no runtime allocation) ----
__device__ float4 g_seg[NS * NSEG];     // per segment: -ax, -ay, bx, by
__device__ float  g_d2[NS * NSEG];      // per segment: bx^2+by^2 (ref rounding)
__device__ float4 g_colw[NS];           // rgb + width packed
__device__ int    g_tidx[NCELL * KNN];  // per coarse cell: sorted top-K stroke ids
__device__ float  g_tw[NCELL * KNN];    // per coarse cell: width of slot-k stroke
__device__ int    g_bincnt[NBINS];      // bin build
__device__ int    g_binstart[NBINS + 1];
__device__ int    g_bincur[NBINS];
__device__ float2 g_binloc[NS];         // stroke locations grouped by bin
__device__ int    g_binidx[NS];         // stroke ids grouped by bin

// ---------------- packed f32x2 helpers (sm_103a; per-element IEEE RN) -------
__device__ __forceinline__ unsigned long long f2pack(float lo, float hi) {
    unsigned long long r;
    asm("mov.b64 %0, {%1, %2};" : "=l"(r) : "f"(lo), "f"(hi));
    return r;
}
__device__ __forceinline__ void f2unpack(unsigned long long v, float& lo, float& hi) {
    asm("mov.b64 {%0, %1}, %2;" : "=f"(lo), "=f"(hi) : "l"(v));
}
__device__ __forceinline__ unsigned long long f2add(unsigned long long a, unsigned long long b) {
    unsigned long long r;
    asm("add.rn.f32x2 %0, %1, %2;" : "=l"(r) : "l"(a), "l"(b));
    return r;
}
__device__ __forceinline__ unsigned long long f2mul(unsigned long long a, unsigned long long b) {
    unsigned long long r;
    asm("mul.rn.f32x2 %0, %1, %2;" : "=l"(r) : "l"(a), "l"(b));
    return r;
}

// Branchless correctly-rounded a/b: the div.rn.f32 fast-path sequence; FCHK
// cases cannot occur for these operand ranges (proven bit-identical R10/R13).
__device__ __forceinline__ float fdiv_exact(float a, float b) {
    float r0;
    asm("rcp.approx.f32 %0, %1;" : "=f"(r0) : "f"(b));
    float e  = __fmaf_rn(-b, r0, 1.0f);
    float r1 = __fmaf_rn(e, r0, r0);
    float q0 = __fmul_rn(a, r1);
    float e2 = __fmaf_rn(-b, q0, a);
    return __fmaf_rn(e2, r1, q0);
}

// ---------------- kernel 0: zero bin counters -------------------------------
__global__ void k_zero() { g_bincnt[threadIdx.x] = 0; }

// ---------------- kernel 1: bezier -> segments (negated a), bin count -------
__global__ void k_bezier(const float* __restrict__ cs, const float* __restrict__ ce,
                         const float* __restrict__ cc, const float* __restrict__ color,
                         const float* __restrict__ loc, const float* __restrict__ width)
{
    int n = blockIdx.x * blockDim.x + threadIdx.x;
    if (n >= NS) return;
    float lx = loc[2*n], ly = loc[2*n+1];
    float Sx = __fadd_rn(cs[2*n],   lx), Sy = __fadd_rn(cs[2*n+1], ly);
    float Ex = __fadd_rn(ce[2*n],   lx), Ey = __fadd_rn(ce[2*n+1], ly);
    float Cx = __fadd_rn(cc[2*n],   lx), Cy = __fadd_rn(cc[2*n+1], ly);
    float dsx = __fsub_rn(Sx, Cx), dsy = __fsub_rn(Sy, Cy);
    float dex = __fsub_rn(Ex, Cx), dey = __fsub_rn(Ey, Cy);
    float step = __fdiv_rn(1.0f, 9.0f);
    float ptx[SPTS], pty[SPTS];
    #pragma unroll
    for (int i = 0; i < SPTS; i++) {
        float t   = __fmul_rn((float)i, step);
        float omt = __fsub_rn(1.0f, t);
        float o2  = __fmul_rn(omt, omt);
        float t2  = __fmul_rn(t, t);
        ptx[i] = __fadd_rn(__fadd_rn(Cx, __fmul_rn(o2, dsx)), __fmul_rn(t2, dex));
        pty[i] = __fadd_rn(__fadd_rn(Cy, __fmul_rn(o2, dsy)), __fmul_rn(t2, dey));
    }
    #pragma unroll
    for (int s = 0; s < NSEG; s++) {
        float bx = __fsub_rn(ptx[s+1], ptx[s]);
        float by = __fsub_rn(pty[s+1], pty[s]);
        g_seg[n*NSEG + s] = make_float4(-ptx[s], -pty[s], bx, by);
        g_d2 [n*NSEG + s] = __fadd_rn(__fmul_rn(bx, bx), __fmul_rn(by, by));
    }
    g_colw[n] = make_float4(color[3*n], color[3*n+1], color[3*n+2], width[n]);

    int bx_ = min(NB-1, (int)(lx * (1.0f/BINW)));
    int by_ = min(NB-1, (int)(ly * (1.0f/BINW)));
    atomicAdd(&g_bincnt[bx_*NB + by_], 1);
}

// ---------------- kernel 2: bin prefix sum (256-thread shfl scan) -----------
__global__ void k_prep() {
    int t = threadIdx.x;                 // 256 threads, one per bin
    int v = g_bincnt[t];
    int lane = t & 31, wp = t >> 5;
    int x = v;
    #pragma unroll
    for (int o = 1; o < 32; o <<= 1) {
        int y = __shfl_up_sync(0xffffffffu, x, o);
        if (lane >= o) x += y;
    }
    __shared__ int wsum[8];
    if (lane == 31) wsum[wp] = x;
    __syncthreads();
    int add = 0;
    #pragma unroll
    for (int i = 0; i < 8; i++) if (i < wp) add += wsum[i];
    int incl = x + add;
    int excl = incl - v;
    g_binstart[t] = excl;
    g_bincur[t]   = excl;
    if (t == NBINS - 1) g_binstart[NBINS] = incl;
}

// ---------------- kernel 3: scatter strokes into bins -----------------------
__global__ void k_scatter(const float* __restrict__ loc) {
    int n = blockIdx.x * blockDim.x + threadIdx.x;
    if (n >= NS) return;
    float lx = loc[2*n], ly = loc[2*n+1];
    int bx_ = min(NB-1, (int)(lx * (1.0f/BINW)));
    int by_ = min(NB-1, (int)(ly * (1.0f/BINW)));
    int pos = atomicAdd(&g_bincur[bx_*NB + by_], 1);
    g_binloc[pos] = make_float2(lx, ly);
    g_binidx[pos] = n;
}

// ---------------- kernel 4: binned coarse-grid top-K ------------------------
#define CPB    64                 // cells per block (128 threads)
__global__ void __launch_bounds__(CPB*2) k_topk(const float* __restrict__ width)
{
    __shared__ float2 sml[CPB][2][KNN];       // (d, idx-bits)

    int c    = threadIdx.x >> 1;              // local cell
    int part = threadIdx.x & 1;
    int cell = blockIdx.x * CPB + c;
    bool active = (cell < NCELL);
    float px = 0.f, py = 0.f;
    int bx = 0, by = 0;
    if (active) {
        int ci = cell / WC, cj = cell % WC;
        float step = __fdiv_rn(512.0f, 101.0f);   // linspace(0,512,102)
        px = __fmul_rn((float)ci, step);
        py = __fmul_rn((float)cj, step);
        bx = min(NB-1, (int)(px * (1.0f/BINW)));
        by = min(NB-1, (int)(py * (1.0f/BINW)));
    }
    float bd[KNN]; int bi[KNN];
    #pragma unroll
    for (int k = 0; k < KNN; k++) { bd[k] = CUDART_INF_F; bi[k] = 0x7fffffff; }

    int t = 0;
    bool done = !active;
    for (int R = 0; R <= NB; R++) {
        if (active && !done) {
            for (int dy2 = -R; dy2 <= R; dy2++) {
                for (int dx2 = -R; dx2 <= R; dx2++) {
                    if (max(abs(dx2), abs(dy2)) != R) continue;
                    int bxx = bx + dx2, byy = by + dy2;
                    if (bxx < 0 || bxx >= NB || byy < 0 || byy >= NB) continue;
                    if (((t++) & 1) != part) continue;
                    int b = bxx*NB + byy;
                    int j0 = g_binstart[b], j1 = g_binstart[b+1];
                    for (int j = j0; j < j1; j++) {
                        float2 L = g_binloc[j];
                        int ii = g_binidx[j];
                        float dx = __fsub_rn(px, L.x);
                        float dy = __fsub_rn(py, L.y);
                        float d  = __fadd_rn(__fmul_rn(dx, dx), __fmul_rn(dy, dy));
                        if (d < bd[KNN-1] || (d == bd[KNN-1] && ii < bi[KNN-1])) {
                            float id = d; int iv = ii;
                            #pragma unroll
                            for (int q = 0; q < KNN; q++) {
                                bool sw = (id < bd[q]) || (id == bd[q] && iv < bi[q]);
                                float td = bd[q]; int ti = bi[q];
                                if (sw) { bd[q] = id; bi[q] = iv; id = td; iv = ti; }
                            }
                        }
                    }
                }
            }
        }
        float m19 = bd[KNN-1];
        float other = __shfl_xor_sync(0xffffffffu, m19, 1);
        float merged = fminf(m19, other);
        float marg = fminf(fminf(px - (float)(bx-R)*BINW, (float)(bx+R+1)*BINW - px),
                           fminf(py - (float)(by-R)*BINW, (float)(by+R+1)*BINW - py));
        marg *= 0.999f;
        bool covered = (bx-R < 0) && (bx+R >= NB-1) && (by-R < 0) && (by+R >= NB-1);
        if (active && !done)
            done = covered || (marg > 0.0f && merged < marg*marg);
        if (__all_sync(0xffffffffu, done)) break;
    }

    __syncthreads();
    #pragma unroll
    for (int k = 0; k < KNN; k++)
        sml[c][part][k] = make_float2(bd[k], __int_as_float(bi[k]));
    __syncthreads();

    if (active && part == 0) {
        int p0 = 0, p1 = 0;
        #pragma unroll
        for (int k = 0; k < KNN; k++) {
            float2 v0 = sml[c][0][p0];
            float2 v1 = sml[c][1][p1];
            float d0 = v0.x; int i0 = __float_as_int(v0.y);
            float d1 = v1.x; int i1 = __float_as_int(v1.y);
            bool take0 = (d0 < d1) || (d0 == d1 && i0 < i1);
            int besti = take0 ? i0 : i1;
            if (take0) p0++; else p1++;
            g_tidx[cell*KNN + k] = besti;
            g_tw  [cell*KNN + k] = __ldg(width + besti);
        }
    }
}

// ---------------- kernel 5: full-res shading, SMEM-STAGED TILE --------------
// Block = 16x16 pixel tile (256 threads, 1 px/thread, 100% lane efficiency).
// The tile touches exactly a 4x4 coarse-cell window; all (cell,k) stroke data
// (seg, d2, colw) plus the 6x6 tw window for the bilinear are staged to smem
// once per block. Inner loop reads LDS (<=2 distinct addrs/warp after the
// 181-stride pad) instead of 4-6-wavefront divergent LDG. Staged values are
// bit-copies; all arithmetic identical -> output bit-identical to R13.
__global__ void __launch_bounds__(256, 2) k_render(float* __restrict__ out)
{
    extern __shared__ char smem[];
    ulonglong2* s_seg = (ulonglong2*)(smem + SM_SEG_OFF);  // [16][SEG_STRIDE]
    float*      s_d2  = (float*)     (smem + SM_D2_OFF);   // [16][SEG_STRIDE]
    float4*     s_cw  = (float4*)    (smem + SM_CW_OFF);   // [16][KNN]
    float*      s_tw  = (float*)     (smem + SM_TW_OFF);   // [6][6][KNN]
    __shared__ int s_idx[16 * KNN];

    int t   = threadIdx.x;
    int bh0 = blockIdx.y * 16, bw0 = blockIdx.x * 16;
    int ch0 = (bh0 * 51) >> 8, cw0 = (bw0 * 51) >> 8;      // cell window origin

    // ---- stage phase 1: stroke ids + tw window (clamped) ----
    for (int i = t; i < 16 * KNN; i += 256) {
        int lc = i / KNN, k = i - lc * KNN;
        int gc = (ch0 + (lc >> 2)) * WC + (cw0 + (lc & 3));
        s_idx[i] = __ldg(g_tidx + gc * KNN + k);
    }
    for (int i = t; i < 36 * KNN; i += 256) {
        int r = i / (6 * KNN), rest = i - r * 6 * KNN;
        int c = rest / KNN, k = rest - c * KNN;
        int gr = max(0, min(HC - 1, ch0 - 1 + r));
        int gc = max(0, min(WC - 1, cw0 - 1 + c));
        s_tw[i] = __ldg(g_tw + (gr * WC + gc) * KNN + k);
    }
    __syncthreads();

    // ---- stage phase 2: segment data + colw by staged ids ----
    for (int i = t; i < 16 * KNN * NSEG; i += 256) {
        int ck = i / NSEG, s = i - ck * NSEG;
        int lc = ck / KNN, ks = (ck - lc * KNN) * NSEG + s;
        int idx = s_idx[ck];
        s_seg[lc * SEG_STRIDE + ks] = __ldg((const ulonglong2*)(g_seg + idx * NSEG + s));
        s_d2 [lc * SEG_STRIDE + ks] = __ldg(g_d2 + idx * NSEG + s);
    }
    for (int i = t; i < 16 * KNN; i += 256)
        s_cw[i] = __ldg(g_colw + s_idx[i]);
    __syncthreads();

    // ---- per-pixel shading ----
    int lh = t >> 4, lw = t & 15;
    int h = bh0 + lh, w = bw0 + lw;

    float stepf = __fdiv_rn(512.0f, 511.0f);   // linspace(0,512,512)
    float pxf = __fmul_rn((float)h, stepf);
    float pyf = __fmul_rn((float)w, stepf);
    unsigned long long P2 = f2pack(pxf, pyf);

    int ch = (h * 51) >> 8, cw = (w * 51) >> 8;            // exact == float floor
    int lcell = ((ch - ch0) << 2) + (cw - cw0);

    // half-pixel bilinear for the width resize (smooth path)
    float yc = ((float)h + 0.5f) * 0.19921875f - 0.5f;
    float xc = ((float)w + 0.5f) * 0.19921875f - 0.5f;
    float y0f = floorf(yc), x0f = floorf(xc);
    float fy = yc - y0f,    fx = xc - x0f;
    int y0 = max(0, min(HC-1, (int)y0f));
    int y1 = max(0, min(HC-1, (int)y0f + 1));
    int x0 = max(0, min(WC-1, (int)x0f));
    int x1 = max(0, min(WC-1, (int)x0f + 1));
    int r0 = y0 - (ch0 - 1), r1 = y1 - (ch0 - 1);
    int c0 = x0 - (cw0 - 1), c1 = x1 - (cw0 - 1);
    const float* tw00 = s_tw + (r0 * 6 + c0) * KNN;
    const float* tw01 = s_tw + (r0 * 6 + c1) * KNN;
    const float* tw10 = s_tw + (r1 * 6 + c0) * KNN;
    const float* tw11 = s_tw + (r1 * 6 + c1) * KNN;
    float c00 = (1.f-fy)*(1.f-fx), c01 = (1.f-fy)*fx;
    float c10 = fy*(1.f-fx),       c11 = fy*fx;

    const ulonglong2* segp = s_seg + lcell * SEG_STRIDE;
    const float*      d2p  = s_d2  + lcell * SEG_STRIDE;
    const float4*     cwp  = s_cw  + lcell * KNN;

    float M = -CUDART_INF_F;
    float sum = 0.f, a0 = 0.f, a1 = 0.f, a2 = 0.f, bw = 0.f;
    float D = CUDART_INF_F;

    #pragma unroll 2
    for (int k = 0; k < KNN; k++) {
        float m = CUDART_INF_F;
        #pragma unroll
        for (int s = 0; s < NSEG; s++) {
            ulonglong2 v = segp[k * NSEG + s];      // LDS.128
            float d2 = d2p[k * NSEG + s];           // LDS.32
            unsigned long long na2 = v.x, b2 = v.y;
            unsigned long long pa2 = f2add(P2, na2);          // fl(P - a)
            unsigned long long pr  = f2mul(b2, pa2);          // fl(b*pa)
            float plo, phi; f2unpack(pr, plo, phi);
            float dot1 = __fadd_rn(plo, phi);
            float tq = fdiv_exact(dot1, d2);
            tq = fminf(fmaxf(tq, 0.0f), 1.0f);
            float nt = __int_as_float(__float_as_int(tq) ^ 0x80000000);
            unsigned long long ntb = f2mul(f2pack(nt, nt), b2);  // -fl(t*b)
            unsigned long long ncl = f2add(na2, ntb);            // -fl(a+tb)
            unsigned long long pc  = f2add(P2, ncl);             // fl(P-closest)
            unsigned long long sq  = f2mul(pc, pc);
            float slo, shi; f2unpack(sq, slo, shi);
            float d = __fadd_rn(slo, shi);
            m = fminf(m, d);
        }
        D = fminf(D, m);

        // r = 100000 * (1 / (1e-8 + m)) — reference rounding (amplified)
        float r = __fmul_rn(100000.0f, __fdiv_rn(1.0f, __fadd_rn(1e-8f, m)));

        float wk = c00*tw00[k] + c01*tw01[k] + c10*tw10[k] + c11*tw11[k];
        float4 col = cwp[k];

        // branchless online softmax (smooth path; fast exp safe)
        float newM = fmaxf(r, M);
        float sc = __expf(M - newM);
        float e  = __expf(r - newM);
        sum = sum*sc + e;
        a0  = a0 *sc + e*col.x;
        a1  = a1 *sc + e*col.y;
        a2  = a2 *sc + e*col.z;
        bw  = bw *sc + e*wk;
        M = newM;
    }

    float inv  = __fdividef(1.0f, sum);
    float bs   = bw * inv;
    float mask = __fdividef(1.0f, 1.0f + __expf(-(bs - D)));
    float om   = 1.0f - mask;
    int o = (h * WW + w) * 3;
    out[o+0] = a0*inv*mask + om*0.5f;
    out[o+1] = a1*inv*mask + om*0.5f;
    out[o+2] = a2*inv*mask + om*0.5f;
}

// ---------------- launch ----------------------------------------------------
extern "C" void kernel_launch(void* const* d_in, const int* in_sizes, int n_in,
                              void* d_out, int out_size)
{
    const float* curve_s  = (const float*)d_in[0];
    const float* curve_e  = (const float*)d_in[1];
    const float* curve_c  = (const float*)d_in[2];
    const float* color    = (const float*)d_in[3];
    const float* location = (const float*)d_in[4];
    const float* width    = (const float*)d_in[5];
    float* out = (float*)d_out;

    cudaFuncSetAttribute(k_render, cudaFuncAttributeMaxDynamicSharedMemorySize, SM_TOTAL);

    k_zero<<<1, NBINS>>>();
    k_bezier<<<(NS + 255) / 256, 256>>>(curve_s, curve_e, curve_c, color, location, width);
    k_prep<<<1, NBINS>>>();
    k_scatter<<<(NS + 255) / 256, 256>>>(location);
    k_topk<<<(NCELL + CPB - 1) / CPB, CPB * 2>>>(width);
    dim3 grid(WW / 16, HH / 16);
    k_render<<<grid, 256, SM_TOTAL>>>(out);
}